// round 1
// baseline (speedup 1.0000x reference)
#include <cuda_runtime.h>

// SSIM loss, fused single-pass kernel.
// Input: pred, target: (16,3,384,512) fp32. Output: scalar fp32 = 1 - mean(ssim_map).
// Valid-padding separable 11-tap gaussian => map is (16,3,374,502).

#define IMG_H 384
#define IMG_W 512
#define OUT_H 374
#define OUT_W 502
#define NC    48            // N*C images
#define TW    64            // output tile width
#define TH    16            // output tile height
#define IW    (TW + 10)     // 74 input cols needed
#define IH    (TH + 10)     // 26 input rows needed
#define SW    75            // smem row stride for input tiles (odd -> no bank conflicts)

__device__ double g_acc;

__global__ void zero_acc_kernel() { g_acc = 0.0; }

__global__ __launch_bounds__(256) void ssim_fused_kernel(
    const float* __restrict__ X, const float* __restrict__ Y)
{
    __shared__ float sx[IH * SW];
    __shared__ float sy[IH * SW];
    __shared__ float hs[5][IH][TW];
    __shared__ float warpsum[8];

    // 11-tap gaussian, sigma=1.5, normalized (matches reference to float precision)
    const float w[11] = {
        0.00102838f, 0.00759876f, 0.03600077f, 0.10936069f, 0.21300553f,
        0.26601172f,
        0.21300553f, 0.10936069f, 0.03600077f, 0.00759876f, 0.00102838f
    };

    const int tid = threadIdx.x;
    const int gx0 = blockIdx.x * TW;
    const int gy0 = blockIdx.y * TH;
    const size_t img_off = (size_t)blockIdx.z * (IMG_H * IMG_W);
    const float* __restrict__ Xi = X + img_off;
    const float* __restrict__ Yi = Y + img_off;

    // ---- Phase 0: load input tile (with zero guard past image edge; those
    // values only feed outputs that are discarded by the bounds check) ----
    for (int i = tid; i < IH * IW; i += 256) {
        int r = i / IW;
        int c = i - r * IW;
        int gr = gy0 + r;
        int gc = gx0 + c;
        float xv = 0.0f, yv = 0.0f;
        if (gr < IMG_H && gc < IMG_W) {
            int o = gr * IMG_W + gc;
            xv = __ldg(Xi + o);
            yv = __ldg(Yi + o);
        }
        sx[r * SW + c] = xv;
        sy[r * SW + c] = yv;
    }
    __syncthreads();

    // ---- Phase 1: horizontal 11-tap conv of {x, y, x^2, y^2, x*y} ----
    // 26 rows x 64 cols positions; warp covers 32 consecutive cols of one row.
    for (int i = tid; i < IH * TW; i += 256) {
        int r = i >> 6;         // /64
        int c = i & 63;
        float s0 = 0.f, s1 = 0.f, s2 = 0.f, s3 = 0.f, s4 = 0.f;
        int base = r * SW + c;
#pragma unroll
        for (int t = 0; t < 11; t++) {
            float xv = sx[base + t];
            float yv = sy[base + t];
            float wt = w[t];
            s0 += wt * xv;
            s1 += wt * yv;
            s2 += wt * xv * xv;
            s3 += wt * yv * yv;
            s4 += wt * xv * yv;
        }
        hs[0][r][c] = s0;
        hs[1][r][c] = s1;
        hs[2][r][c] = s2;
        hs[3][r][c] = s3;
        hs[4][r][c] = s4;
    }
    __syncthreads();

    // ---- Phase 2: vertical conv + SSIM. Thread (tx, ty) owns column tx,
    // output rows ty*4 .. ty*4+3; each loaded hs row feeds up to 4 accumulators.
    const int tx = tid & 63;
    const int ty = tid >> 6;    // 0..3

    float acc[4][5];
#pragma unroll
    for (int k = 0; k < 4; k++)
#pragma unroll
        for (int ch = 0; ch < 5; ch++) acc[k][ch] = 0.0f;

#pragma unroll
    for (int rr = 0; rr < 14; rr++) {
        int r = ty * 4 + rr;
        float v0 = hs[0][r][tx];
        float v1 = hs[1][r][tx];
        float v2 = hs[2][r][tx];
        float v3 = hs[3][r][tx];
        float v4 = hs[4][r][tx];
#pragma unroll
        for (int k = 0; k < 4; k++) {
            int t = rr - k;
            if (t >= 0 && t < 11) {
                float wt = w[t];
                acc[k][0] += wt * v0;
                acc[k][1] += wt * v1;
                acc[k][2] += wt * v2;
                acc[k][3] += wt * v3;
                acc[k][4] += wt * v4;
            }
        }
    }

    const float C1 = 1e-4f;   // (0.01*1.0)^2
    const float C2 = 9e-4f;   // (0.03*1.0)^2
    float lsum = 0.0f;
    const int gc = gx0 + tx;
#pragma unroll
    for (int k = 0; k < 4; k++) {
        int gr = gy0 + ty * 4 + k;
        if (gr < OUT_H && gc < OUT_W) {
            float mu1 = acc[k][0];
            float mu2 = acc[k][1];
            float m11 = mu1 * mu1;
            float m22 = mu2 * mu2;
            float m12 = mu1 * mu2;
            float sg1 = acc[k][2] - m11;
            float sg2 = acc[k][3] - m22;
            float s12 = acc[k][4] - m12;
            float num = (2.0f * m12 + C1) * (2.0f * s12 + C2);
            float den = (m11 + m22 + C1) * (sg1 + sg2 + C2);
            lsum += __fdividef(num, den);
        }
    }

    // ---- Block reduction -> one double atomic per block ----
#pragma unroll
    for (int o = 16; o > 0; o >>= 1)
        lsum += __shfl_down_sync(0xffffffffu, lsum, o);
    if ((tid & 31) == 0) warpsum[tid >> 5] = lsum;
    __syncthreads();
    if (tid == 0) {
        double s = 0.0;
#pragma unroll
        for (int i = 0; i < 8; i++) s += (double)warpsum[i];
        atomicAdd(&g_acc, s);
    }
}

__global__ void finalize_kernel(float* __restrict__ out)
{
    double cnt = (double)NC * (double)OUT_H * (double)OUT_W;  // 9,011,904
    out[0] = (float)(1.0 - g_acc / cnt);
}

extern "C" void kernel_launch(void* const* d_in, const int* in_sizes, int n_in,
                              void* d_out, int out_size)
{
    (void)in_sizes; (void)n_in; (void)out_size;
    const float* pred   = (const float*)d_in[0];
    const float* target = (const float*)d_in[1];
    float* out = (float*)d_out;

    zero_acc_kernel<<<1, 1>>>();

    dim3 grid((OUT_W + TW - 1) / TW,   // 8
              (OUT_H + TH - 1) / TH,   // 24
              NC);                     // 48
    ssim_fused_kernel<<<grid, 256>>>(pred, target);

    finalize_kernel<<<1, 1>>>(out);
}

// round 7
// speedup vs baseline: 1.2332x; 1.2332x over previous
#include <cuda_runtime.h>

// Fused SSIM loss — single kernel, row-streaming column strips.
// pred/target: (16,3,384,512) fp32; out: scalar fp32 = 1 - mean(ssim_map),
// ssim map (48, 374, 502) with 11-tap separable gaussian, VALID padding.

#define IMG_H 384
#define IMG_W 512
#define OUT_H 374
#define OUT_W 502
#define TW    64        // output cols per block
#define IWD   74        // input cols per block (TW + 10)
#define SSTR  75        // staging row stride (odd -> conflict-free)
#define G     16        // output rows per iteration
#define NITER 24        // ceil(374/16)
#define RINGN 26        // ring rows (window span exactly 26)
#define NBLK  (8*48)

__device__ double g_acc;           // zero-init; reset by last block each run
__device__ unsigned int g_count;   // zero-init; reset by last block each run

__global__ __launch_bounds__(256, 3)
void ssim_stream_kernel(const float* __restrict__ X,
                        const float* __restrict__ Y,
                        float* __restrict__ out)
{
    __shared__ float stx[RINGN][SSTR];
    __shared__ float sty[RINGN][SSTR];
    __shared__ float hs[5][RINGN][TW];
    __shared__ float warpsum[8];

    // 11-tap gaussian (sigma=1.5), normalized; validated in round 1.
    const float w[11] = {
        0.00102838f, 0.00759876f, 0.03600077f, 0.10936069f, 0.21300553f,
        0.26601172f,
        0.21300553f, 0.10936069f, 0.03600077f, 0.00759876f, 0.00102838f
    };

    const int tid = threadIdx.x;
    const int gx0 = blockIdx.x * TW;
    const size_t off = (size_t)blockIdx.y * (IMG_H * IMG_W);
    const float* __restrict__ Xi = X + off;
    const float* __restrict__ Yi = Y + off;

    const int tx   = tid & 63;      // phase-2 column
    const int jrow = tid >> 6;      // phase-2 row-group 0..3
    const int gc   = gx0 + tx;

    float lsum = 0.0f;

    // ---- Prologue: stage input rows 0..25 ----
    for (int i = tid; i < 26 * IWD; i += 256) {
        int r = i / IWD;
        int c = i - r * IWD;
        int gcol = gx0 + c;
        float xv = 0.f, yv = 0.f;
        if (gcol < IMG_W) {
            int o = r * IMG_W + gcol;
            xv = __ldg(Xi + o);
            yv = __ldg(Yi + o);
        }
        stx[r][c] = xv;             // rows 0..25 map to slots 0..25
        sty[r][c] = yv;
    }
    __syncthreads();

    // ---- Prologue phase 1: horizontal conv, hs rows 0..25 ----
    for (int i = tid; i < 26 * 16; i += 256) {
        int rr = i >> 4;
        int cg = (i & 15) << 2;
        int s  = rr;                // rr < 26
        float acc[4][5];
#pragma unroll
        for (int k = 0; k < 4; k++)
#pragma unroll
            for (int ch = 0; ch < 5; ch++) acc[k][ch] = 0.f;
#pragma unroll
        for (int t = 0; t < 14; t++) {
            float xv = stx[s][cg + t];
            float yv = sty[s][cg + t];
            float xx = xv * xv, yy = yv * yv, xy = xv * yv;
#pragma unroll
            for (int k = 0; k < 4; k++) {
                int u = t - k;
                if (u >= 0 && u < 11) {
                    float wt = w[u];
                    acc[k][0] += wt * xv; acc[k][1] += wt * yv;
                    acc[k][2] += wt * xx; acc[k][3] += wt * yy;
                    acc[k][4] += wt * xy;
                }
            }
        }
#pragma unroll
        for (int ch = 0; ch < 5; ch++) {
            float4 v;
            v.x = acc[0][ch]; v.y = acc[1][ch]; v.z = acc[2][ch]; v.w = acc[3][ch];
            *reinterpret_cast<float4*>(&hs[ch][s][cg]) = v;
        }
    }
    __syncthreads();

    // ---- Main loop: 24 iterations of 16 output rows ----
    for (int it = 0; it < NITER; it++) {
        // (a) stage next 16 input rows (for next phase 1); skip on last iter
        if (it < NITER - 1) {
            int r0 = 26 + it * G;
            for (int i = tid; i < G * IWD; i += 256) {
                int r = i / IWD;
                int c = i - r * IWD;
                int grow = r0 + r;
                int gcol = gx0 + c;
                float xv = 0.f, yv = 0.f;
                if (grow < IMG_H && gcol < IMG_W) {
                    int o = grow * IMG_W + gcol;
                    xv = __ldg(Xi + o);
                    yv = __ldg(Yi + o);
                }
                int s = grow % RINGN;
                stx[s][c] = xv;
                sty[s][c] = yv;
            }
        }

        // (b) phase 2: vertical conv + SSIM for out rows it*16 + jrow*4 .. +3
        {
            int base = it * G + jrow * 4;
            float acc[4][5];
#pragma unroll
            for (int k = 0; k < 4; k++)
#pragma unroll
                for (int ch = 0; ch < 5; ch++) acc[k][ch] = 0.f;

            int s = base % RINGN;
#pragma unroll
            for (int rr = 0; rr < 14; rr++) {
                float v0 = hs[0][s][tx];
                float v1 = hs[1][s][tx];
                float v2 = hs[2][s][tx];
                float v3 = hs[3][s][tx];
                float v4 = hs[4][s][tx];
#pragma unroll
                for (int k = 0; k < 4; k++) {
                    int t = rr - k;
                    if (t >= 0 && t < 11) {
                        float wt = w[t];
                        acc[k][0] += wt * v0; acc[k][1] += wt * v1;
                        acc[k][2] += wt * v2; acc[k][3] += wt * v3;
                        acc[k][4] += wt * v4;
                    }
                }
                s++; if (s == RINGN) s = 0;
            }

            const float C1 = 1e-4f;
            const float C2 = 9e-4f;
#pragma unroll
            for (int k = 0; k < 4; k++) {
                int orow = base + k;
                if (orow < OUT_H && gc < OUT_W) {
                    float mu1 = acc[k][0], mu2 = acc[k][1];
                    float m11 = mu1 * mu1, m22 = mu2 * mu2, m12 = mu1 * mu2;
                    float s12 = acc[k][4] - m12;
                    float sg1 = acc[k][2] - m11;
                    float sg2 = acc[k][3] - m22;
                    float num = (2.0f * m12 + C1) * (2.0f * s12 + C2);
                    float den = (m11 + m22 + C1) * (sg1 + sg2 + C2);
                    lsum += __fdividef(num, den);
                }
            }
        }
        __syncthreads();

        // (c) phase 1: horizontal conv for hs rows 26+it*16 .. 41+it*16
        if (it < NITER - 1) {
            int h0 = 26 + it * G;
            {
                int i = tid;                 // exactly 256 items
                int rr = i >> 4;
                int cg = (i & 15) << 2;
                int h = h0 + rr;
                int s = h % RINGN;
                float acc[4][5];
#pragma unroll
                for (int k = 0; k < 4; k++)
#pragma unroll
                    for (int ch = 0; ch < 5; ch++) acc[k][ch] = 0.f;
#pragma unroll
                for (int t = 0; t < 14; t++) {
                    float xv = stx[s][cg + t];
                    float yv = sty[s][cg + t];
                    float xx = xv * xv, yy = yv * yv, xy = xv * yv;
#pragma unroll
                    for (int k = 0; k < 4; k++) {
                        int u = t - k;
                        if (u >= 0 && u < 11) {
                            float wt = w[u];
                            acc[k][0] += wt * xv; acc[k][1] += wt * yv;
                            acc[k][2] += wt * xx; acc[k][3] += wt * yy;
                            acc[k][4] += wt * xy;
                        }
                    }
                }
#pragma unroll
                for (int ch = 0; ch < 5; ch++) {
                    float4 v;
                    v.x = acc[0][ch]; v.y = acc[1][ch];
                    v.z = acc[2][ch]; v.w = acc[3][ch];
                    *reinterpret_cast<float4*>(&hs[ch][s][cg]) = v;
                }
            }
        }
        __syncthreads();
    }

    // ---- Block reduction, global accumulation, fused finalize ----
#pragma unroll
    for (int o = 16; o > 0; o >>= 1)
        lsum += __shfl_down_sync(0xffffffffu, lsum, o);
    if ((tid & 31) == 0) warpsum[tid >> 5] = lsum;
    __syncthreads();
    if (tid == 0) {
        double s = 0.0;
#pragma unroll
        for (int i = 0; i < 8; i++) s += (double)warpsum[i];
        atomicAdd(&g_acc, s);
        __threadfence();
        unsigned int old = atomicAdd(&g_count, 1u);
        if (old == NBLK - 1) {
            __threadfence();
            double cnt = (double)48 * (double)OUT_H * (double)OUT_W;
            out[0] = (float)(1.0 - g_acc / cnt);
            // reset for next graph replay (deterministic)
            g_acc = 0.0;
            g_count = 0u;
        }
    }
}

extern "C" void kernel_launch(void* const* d_in, const int* in_sizes, int n_in,
                              void* d_out, int out_size)
{
    (void)in_sizes; (void)n_in; (void)out_size;
    const float* pred   = (const float*)d_in[0];
    const float* target = (const float*)d_in[1];
    float* out = (float*)d_out;

    dim3 grid(8, 48);   // 8 column strips x 48 images = 384 blocks
    ssim_stream_kernel<<<grid, 256>>>(pred, target, out);
}